// round 16
// baseline (speedup 1.0000x reference)
#include <cuda_runtime.h>
#include <math.h>
#include <stdint.h>

#define NP 8732
#define NC 21
#define NB 128
#define NO 32
#define THRESH 0.5f
#define ALPHA 10.0

// K1: IoU kernel decomposition (18 chunks of 512 for 4 blocks/SM)
#define NCHI 18
#define CPI  512              // 18*512 = 9216 >= 8732 (padded)
#define K1_TPB 256
#define K1_PPT 2

// K2: CE kernel decomposition (groups of 4 priors)
#define NG  2183              // 8732/4
#define NCHC 4
#define GPC 546               // groups per chunk
#define K2_TPB 256
#define K2_GPT 3

// K3
#define K3_TPB 512
#define K3_VPT 18             // ceil(8732/512)

// -------- device scratch (all fully rewritten every launch) --------
__device__ unsigned long long g_objc[NB * NO * NCHI]; // per-chunk (iou<<32)|~prior
__device__ unsigned g_pbest[NB * NP];                 // packed (iou&~31)|(31-m)
__device__ float  g_ce[NB * NP];                      // CE of negatives (0 for pos)
__device__ int    g_npc[NB * NCHC];
__device__ double g_cpc[NB * NCHC];
__device__ double g_locc[NB * NCHC];
__device__ double g_hard[NB];
__device__ unsigned g_done = 0;                       // self-resetting

// ---------------------------------------------------------
// K1: per-chunk IoU pass. grid = (NCHI, NB), 256 threads, 4 blocks/SM.
// ---------------------------------------------------------
__global__ __launch_bounds__(K1_TPB, 4)
void iou_k(const float* __restrict__ b_boxes,
           const float* __restrict__ priors) {
    const int chunk = blockIdx.x;
    const int b     = blockIdx.y;
    const int tid   = threadIdx.x;
    const int lane  = tid & 31;
    const int wid   = tid >> 5;       // 0..7
    const int base  = chunk * CPI;

    __shared__ float sbx1[NO], sby1[NO], sbx2[NO], sby2[NO], sba[NO];
    __shared__ float swv2[NO][8];     // per-warp per-object partial max
    __shared__ int   swi2[NO][8];

    if (tid < NO) {
        const float* bb = b_boxes + ((size_t)b * NO + tid) * 4;
        float x1 = bb[0], y1 = bb[1], x2 = bb[2], y2 = bb[3];
        sbx1[tid] = x1; sby1[tid] = y1; sbx2[tid] = x2; sby2[tid] = y2;
        sba[tid]  = (x2 - x1) * (y2 - y1);
    }
    __syncthreads();

    // prior corners in registers; invalid slots degenerate (IoU == 0 exactly,
    // index larger than any valid prior -> can never win a min-index tie)
    float px1[K1_PPT], py1[K1_PPT], px2[K1_PPT], py2[K1_PPT], pa[K1_PPT];
    #pragma unroll
    for (int i = 0; i < K1_PPT; i++) {
        int p = base + tid + i * K1_TPB;
        if (p < NP) {
            float4 pc = reinterpret_cast<const float4*>(priors)[p];
            float hw = pc.z * 0.5f, hh = pc.w * 0.5f;
            px1[i] = pc.x - hw; py1[i] = pc.y - hh;
            px2[i] = pc.x + hw; py2[i] = pc.y + hh;
            pa[i]  = (px2[i] - px1[i]) * (py2[i] - py1[i]);
        } else {
            px1[i] = 2.0f; py1[i] = 2.0f; px2[i] = 2.0f; py2[i] = 2.0f;
            pa[i]  = 0.0f;
        }
    }

    unsigned pkey[K1_PPT];            // per-prior best over objects
    #pragma unroll
    for (int i = 0; i < K1_PPT; i++) pkey[i] = 0u;

    for (int g = 0; g < NO / 4; ++g) {
        float B1[4], B2[4], B3[4], B4[4], BA[4];
        #pragma unroll
        for (int j = 0; j < 4; j++) {
            int m = g * 4 + j;
            B1[j] = sbx1[m]; B2[j] = sby1[m];
            B3[j] = sbx2[m]; B4[j] = sby2[m]; BA[j] = sba[m];
        }
        // per-object within-thread argmax, packed EXACTLY:
        // key = (iou_bits << 1) | (1 - i); iou <= 1.0 so no overflow;
        // equal iou -> i=0 (smaller p) wins under unsigned max.
        unsigned obk[4] = {0u, 0u, 0u, 0u};

        #pragma unroll
        for (int i = 0; i < K1_PPT; i++) {
            #pragma unroll
            for (int j = 0; j < 4; j++) {
                float ix1 = fmaxf(B1[j], px1[i]), iy1 = fmaxf(B2[j], py1[i]);
                float ix2 = fminf(B3[j], px2[i]), iy2 = fminf(B4[j], py2[i]);
                float iw  = __saturatef(ix2 - ix1);   // FADD.SAT (fma pipe)
                float ih  = __saturatef(iy2 - iy1);
                float inter = iw * ih;
                float uni   = (BA[j] + pa[i]) - inter;
                float iou   = __fdividef(inter, uni);
                unsigned ib = __float_as_uint(iou);
                // per-prior argmax over objects (truncated tie window 2^-19)
                unsigned k = (ib & 0xFFFFFFE0u) | (unsigned)(31 - (g * 4 + j));
                pkey[i] = (k > pkey[i]) ? k : pkey[i];
                // per-object argmax over this thread's priors (exact)
                unsigned ko = (ib << 1) | (unsigned)(1 - i);
                obk[j] = (ko > obk[j]) ? ko : obk[j];
            }
        }
        // warp-level per-object argmax; lane0 writes its PRIVATE smem column
        #pragma unroll
        for (int j = 0; j < 4; j++) {
            float v = __uint_as_float(obk[j] >> 1);
            int   ix = base + tid + (int)(1u - (obk[j] & 1u)) * K1_TPB;
            #pragma unroll
            for (int o = 16; o > 0; o >>= 1) {
                float v2 = __shfl_down_sync(0xffffffffu, v, o);
                int   i2 = __shfl_down_sync(0xffffffffu, ix, o);
                if (v2 > v || (v2 == v && i2 < ix)) { v = v2; ix = i2; }
            }
            if (lane == 0) { swv2[g * 4 + j][wid] = v; swi2[g * 4 + j][wid] = ix; }
        }
        // NO syncthreads here: each warp owns column [*][wid]
    }

    __syncthreads();
    // cross-warp reduce: 256 threads = 32 objects x 8 warp-slots
    {
        int obj = tid >> 3, w = tid & 7;
        float v = swv2[obj][w];
        int   ix = swi2[obj][w];
        #pragma unroll
        for (int o = 4; o > 0; o >>= 1) {
            float v2 = __shfl_down_sync(0xffffffffu, v, o, 8);
            int   i2 = __shfl_down_sync(0xffffffffu, ix, o, 8);
            if (v2 > v || (v2 == v && i2 < ix)) { v = v2; ix = i2; }
        }
        if (w == 0) {
            unsigned long long pk =
                ((unsigned long long)__float_as_uint(v) << 32) | (unsigned)(~ix);
            g_objc[((size_t)b * NO + obj) * NCHI + chunk] = pk;
        }
    }

    #pragma unroll
    for (int i = 0; i < K1_PPT; i++) {
        int p = base + tid + i * K1_TPB;
        if (p < NP) g_pbest[(size_t)b * NP + p] = pkey[i];
    }
}

// ---------------------------------------------------------
// K2: match fix-up + CE + loc. grid = (NCHC, NB), 256 threads.
// ---------------------------------------------------------
__global__ __launch_bounds__(K2_TPB, 4)
void ce_k(const float* __restrict__ pred_loc,
          const float* __restrict__ pred_cls,
          const float* __restrict__ b_boxes,
          const int*   __restrict__ b_labels,
          const float* __restrict__ priors) {
    const int chunk = blockIdx.x;
    const int b     = blockIdx.y;
    const int tid   = threadIdx.x;
    const int lane  = tid & 31;
    const int wid   = tid >> 5;       // 0..7
    const int gbase = chunk * GPC;
    const int pbase = gbase * 4;
    const int pcount = min(NP - pbase, GPC * 4);

    __shared__ float sbx1[NO], sby1[NO], sbx2[NO], sby2[NO];
    __shared__ int   slab[NO];
    __shared__ unsigned long long spk[NO];
    __shared__ unsigned char sov[GPC * 4];
    __shared__ int    siw[8];
    __shared__ double sdw[8], sdw2[8];

    if (tid < NO) {
        const float* bb = b_boxes + ((size_t)b * NO + tid) * 4;
        sbx1[tid] = bb[0]; sby1[tid] = bb[1]; sbx2[tid] = bb[2]; sby2[tid] = bb[3];
        slab[tid] = b_labels[b * NO + tid];
        unsigned long long mx = 0ULL;
        #pragma unroll
        for (int ch = 0; ch < NCHI; ch++) {
            unsigned long long v = g_objc[((size_t)b * NO + tid) * NCHI + ch];
            if (v > mx) mx = v;
        }
        spk[tid] = mx;
    }
    for (int i = tid; i < pcount; i += K2_TPB) sov[i] = 255;
    __syncthreads();
    if (tid == 0) {
        for (int m = NO - 1; m >= 0; --m) {     // descending: min m wins
            int p = (int)(~(unsigned)(spk[m] & 0xffffffffu));
            int r = p - pbase;
            if (r >= 0 && r < pcount) sov[r] = (unsigned char)m;
        }
    }
    __syncthreads();

    int    npl  = 0;
    double cpl  = 0.0;
    double locl = 0.0;

    #pragma unroll
    for (int it = 0; it < K2_GPT; it++) {
        int gl  = tid + it * K2_TPB;
        int grp = gbase + gl;
        if (gl < GPC && grp < NG) {
            uint4 pk4 = *reinterpret_cast<const uint4*>(
                g_pbest + (size_t)b * NP + (size_t)grp * 4);
            unsigned pkj[4] = {pk4.x, pk4.y, pk4.z, pk4.w};

            int  cls[4]; bool pos[4]; int bm[4];
            #pragma unroll
            for (int j = 0; j < 4; j++) {
                int p = grp * 4 + j;
                float bv = __uint_as_float(pkj[j] & 0xFFFFFFE0u);
                int   m  = 31 - (int)(pkj[j] & 31u);
                int ov = sov[p - pbase];
                if (ov != 255) {
                    if (bv < 1.0f || (bv == 1.0f && ov < m)) { bv = 1.0f; m = ov; }
                }
                pos[j] = (bv >= THRESH);
                bm[j]  = m;
                cls[j] = pos[j] ? slab[m] : 0;
            }

            const float4* basep = reinterpret_cast<const float4*>(
                pred_cls + ((size_t)b * NP + (size_t)grp * 4) * NC);
            float se[4] = {0.f, 0.f, 0.f, 0.f};
            float lc[4] = {0.f, 0.f, 0.f, 0.f};
            #pragma unroll
            for (int k = 0; k < NC; k++) {       // 21 float4 = 84 logits
                float4 v = basep[k];
                {   int e = 4 * k + 0, r = e / NC, c = e % NC;
                    se[r] += __expf(v.x); if (c == cls[r]) lc[r] = v.x; }
                {   int e = 4 * k + 1, r = e / NC, c = e % NC;
                    se[r] += __expf(v.y); if (c == cls[r]) lc[r] = v.y; }
                {   int e = 4 * k + 2, r = e / NC, c = e % NC;
                    se[r] += __expf(v.z); if (c == cls[r]) lc[r] = v.z; }
                {   int e = 4 * k + 3, r = e / NC, c = e % NC;
                    se[r] += __expf(v.w); if (c == cls[r]) lc[r] = v.w; }
            }

            float cearr[4];
            #pragma unroll
            for (int j = 0; j < 4; j++) {
                int p = grp * 4 + j;
                float ce = __logf(se[j]) - lc[j];
                if (pos[j]) {
                    cearr[j] = 0.0f;
                    npl++;
                    cpl += (double)ce;
                    float4 pc = reinterpret_cast<const float4*>(priors)[p];
                    int m = bm[j];
                    float x1 = sbx1[m], y1 = sby1[m], x2 = sbx2[m], y2 = sby2[m];
                    float cx = (x1 + x2) * 0.5f, cy = (y1 + y2) * 0.5f;
                    float bw = x2 - x1, bh = y2 - y1;
                    float gx = (cx - pc.x) / (pc.z / 10.0f);
                    float gy = (cy - pc.y) / (pc.w / 10.0f);
                    float gw = __logf(bw / pc.z) * 5.0f;
                    float gh = __logf(bh / pc.w) * 5.0f;
                    float4 pl = reinterpret_cast<const float4*>(pred_loc)[(size_t)b * NP + p];
                    locl += (double)(fabsf(pl.x - gx) + fabsf(pl.y - gy) +
                                     fabsf(pl.z - gw) + fabsf(pl.w - gh));
                } else {
                    cearr[j] = fmaxf(ce, 0.0f);
                }
            }
            *reinterpret_cast<float4*>(g_ce + (size_t)b * NP + (size_t)grp * 4) =
                make_float4(cearr[0], cearr[1], cearr[2], cearr[3]);
        }
    }

    // block reduce -> per-chunk plain stores (no atomics, deterministic)
    #pragma unroll
    for (int o = 16; o > 0; o >>= 1) {
        npl  += __shfl_down_sync(0xffffffffu, npl, o);
        cpl  += __shfl_down_sync(0xffffffffu, cpl, o);
        locl += __shfl_down_sync(0xffffffffu, locl, o);
    }
    if (lane == 0) { siw[wid] = npl; sdw[wid] = cpl; sdw2[wid] = locl; }
    __syncthreads();
    if (tid == 0) {
        int n = 0; double c = 0.0, l = 0.0;
        #pragma unroll
        for (int w = 0; w < 8; w++) { n += siw[w]; c += sdw[w]; l += sdw2[w]; }
        g_npc[b * NCHC + chunk]  = n;
        g_cpc[b * NCHC + chunk]  = c;
        g_locc[b * NCHC + chunk] = l;
    }
}

// ---------------------------------------------------------
// K3: exact top-K via register radix select (REDUX counts) + fused finalize.
// grid = NB, 512 threads.
// ---------------------------------------------------------
__global__ __launch_bounds__(K3_TPB)
void hard_k(float* __restrict__ out) {
    const int b    = blockIdx.x;
    const int tid  = threadIdx.x;
    const int lane = tid & 31;
    const int wid  = tid >> 5;      // 0..15

    __shared__ int    sscnt[32];
    __shared__ int    siw[16];
    __shared__ double sdw[16];
    __shared__ double sl2[16];
    __shared__ bool   s_last;

    unsigned v[K3_VPT];
    #pragma unroll
    for (int i = 0; i < K3_VPT; i++) {
        int p = tid + i * K3_TPB;
        v[i] = (p < NP) ? __float_as_uint(g_ce[(size_t)b * NP + p]) : 0u;
    }
    if (tid < 32) sscnt[tid] = 0;
    int K = g_npc[b * NCHC + 0] + g_npc[b * NCHC + 1]
          + g_npc[b * NCHC + 2] + g_npc[b * NCHC + 3];
    K *= 3;
    if (K > NP) K = NP;
    __syncthreads();

    unsigned t = 0u;
    for (int bit = 30; bit >= 0; --bit) {
        unsigned cand = t | (1u << bit);
        int c = 0;
        #pragma unroll
        for (int i = 0; i < K3_VPT; i++)
            if (v[i] >= cand) c++;
        c = __reduce_add_sync(0xffffffffu, c);   // REDUX.SUM: 1 instr
        if (lane == 0 && c) atomicAdd(&sscnt[bit], c);
        __syncthreads();
        if (sscnt[bit] >= K) t = cand;
        // next pass uses a different counter slot -> single sync per pass
    }

    int    cgt = 0;
    double sg  = 0.0;
    #pragma unroll
    for (int i = 0; i < K3_VPT; i++) {
        if (v[i] > t) { cgt++; sg += (double)__uint_as_float(v[i]); }
    }
    cgt = __reduce_add_sync(0xffffffffu, cgt);
    #pragma unroll
    for (int o = 16; o > 0; o >>= 1)
        sg += __shfl_down_sync(0xffffffffu, sg, o);
    if (lane == 0) { siw[wid] = cgt; sdw[wid] = sg; }
    __syncthreads();
    if (tid == 0) {
        int c = 0; double sm = 0.0;
        #pragma unroll
        for (int w = 0; w < 16; w++) { c += siw[w]; sm += sdw[w]; }
        g_hard[b] = sm + (double)(K - c) * (double)__uint_as_float(t);
        __threadfence();
        unsigned n = atomicAdd(&g_done, 1u);
        s_last = (n == NB - 1);
    }
    __syncthreads();

    // ---- last block: final reduction (replaces finalize kernel) ----
    if (s_last) {
        if (tid == 0) g_done = 0;   // reset for next graph replay
        double h = 0.0, l = 0.0; int n = 0;
        if (tid < NB) {
            h = g_hard[tid];
            #pragma unroll
            for (int ch = 0; ch < NCHC; ch++) {
                h += g_cpc[tid * NCHC + ch];
                l += g_locc[tid * NCHC + ch];
                n += g_npc[tid * NCHC + ch];
            }
        }
        #pragma unroll
        for (int o = 16; o > 0; o >>= 1) {
            h += __shfl_down_sync(0xffffffffu, h, o);
            l += __shfl_down_sync(0xffffffffu, l, o);
            n += __shfl_down_sync(0xffffffffu, n, o);
        }
        if (lane == 0) { sdw[wid] = h; sl2[wid] = l; siw[wid] = n; }
        __syncthreads();
        if (tid == 0) {
            double H = 0.0, L = 0.0, N = 0.0;
            #pragma unroll
            for (int w = 0; w < 16; w++) { H += sdw[w]; L += sl2[w]; N += (double)siw[w]; }
            double loc  = ALPHA * (L / (N * 4.0));
            double conf = H / N;
            out[0] = (float)(conf + loc);
            out[1] = (float)loc;
            out[2] = (float)conf;
        }
    }
}

extern "C" void kernel_launch(void* const* d_in, const int* in_sizes, int n_in,
                              void* d_out, int out_size) {
    const float* pred_loc = (const float*)d_in[0];
    const float* pred_cls = (const float*)d_in[1];
    const float* b_boxes  = (const float*)d_in[2];
    const int*   b_labels = (const int*)  d_in[3];
    const float* priors   = (const float*)d_in[4];
    float* out = (float*)d_out;

    iou_k<<<dim3(NCHI, NB), K1_TPB>>>(b_boxes, priors);
    ce_k<<<dim3(NCHC, NB), K2_TPB>>>(pred_loc, pred_cls, b_boxes, b_labels, priors);
    hard_k<<<NB, K3_TPB>>>(out);
}

// round 17
// speedup vs baseline: 1.1643x; 1.1643x over previous
#include <cuda_runtime.h>
#include <math.h>
#include <stdint.h>

#define NP 8732
#define NC 21
#define NB 128
#define NO 32
#define THRESH 0.5f
#define ALPHA 10.0

// K1: IoU kernel decomposition (R14 proven config)
#define NCHI 8
#define CPI  1092             // 8*1092 = 8736 >= 8732 (padded)
#define K1_TPB 256
#define K1_PPT 5

// K2: CE kernel, chunks aligned to 4 priors for float4 staging
#define NCHC 4
#define CPC0 2184             // chunks 0..2; chunk 3 = 8732-3*2184 = 2180
#define K2_TPB 256
#define K2_ITERS 9            // ceil(2184/256)

// K3
#define K3_TPB 512
#define K3_VPT 18             // ceil(8732/512)

// -------- device scratch (all fully rewritten every launch) --------
__device__ unsigned long long g_objc[NB * NO * NCHI]; // per-chunk (iou<<32)|~prior
__device__ unsigned g_pbest[NB * NP];                 // packed (iou&~31)|(31-m)
__device__ float  g_ce[NB * NP];                      // CE of negatives (0 for pos)
__device__ int    g_npc[NB * NCHC];
__device__ double g_cpc[NB * NCHC];
__device__ double g_locc[NB * NCHC];
__device__ double g_hard[NB];
__device__ unsigned g_done = 0;                       // self-resetting

// ---------------------------------------------------------
// K1: per-chunk IoU pass (R14 exact). grid = (NCHI, NB), 256 thr, 3 blk/SM.
// ---------------------------------------------------------
__global__ __launch_bounds__(K1_TPB, 3)
void iou_k(const float* __restrict__ b_boxes,
           const float* __restrict__ priors) {
    const int chunk = blockIdx.x;
    const int b     = blockIdx.y;
    const int tid   = threadIdx.x;
    const int lane  = tid & 31;
    const int wid   = tid >> 5;       // 0..7
    const int base  = chunk * CPI;

    __shared__ float sbx1[NO], sby1[NO], sbx2[NO], sby2[NO], sba[NO];
    __shared__ float swv[4][8];
    __shared__ int   swi[4][8];

    if (tid < NO) {
        const float* bb = b_boxes + ((size_t)b * NO + tid) * 4;
        float x1 = bb[0], y1 = bb[1], x2 = bb[2], y2 = bb[3];
        sbx1[tid] = x1; sby1[tid] = y1; sbx2[tid] = x2; sby2[tid] = y2;
        sba[tid]  = (x2 - x1) * (y2 - y1);
    }
    __syncthreads();

    // prior corners in registers; padded priors degenerate (IoU exactly 0,
    // cannot win min-index ties against any real candidate)
    float px1[K1_PPT], py1[K1_PPT], px2[K1_PPT], py2[K1_PPT], pa[K1_PPT];
    #pragma unroll
    for (int i = 0; i < K1_PPT; i++) {
        int p = base + tid + i * K1_TPB;
        if (p < NP && tid + i * K1_TPB < CPI) {
            float4 pc = reinterpret_cast<const float4*>(priors)[p];
            float hw = pc.z * 0.5f, hh = pc.w * 0.5f;
            px1[i] = pc.x - hw; py1[i] = pc.y - hh;
            px2[i] = pc.x + hw; py2[i] = pc.y + hh;
            pa[i]  = (px2[i] - px1[i]) * (py2[i] - py1[i]);
        } else {
            px1[i] = 2.0f; py1[i] = 2.0f; px2[i] = 2.0f; py2[i] = 2.0f;
            pa[i]  = 0.0f;
        }
    }

    unsigned pkey[K1_PPT];
    #pragma unroll
    for (int i = 0; i < K1_PPT; i++) pkey[i] = 0u;

    for (int g = 0; g < NO / 4; ++g) {
        float B1[4], B2[4], B3[4], B4[4], BA[4];
        #pragma unroll
        for (int j = 0; j < 4; j++) {
            int m = g * 4 + j;
            B1[j] = sbx1[m]; B2[j] = sby1[m];
            B3[j] = sbx2[m]; B4[j] = sby2[m]; BA[j] = sba[m];
        }
        float obv[4]; int obi[4];
        #pragma unroll
        for (int j = 0; j < 4; j++) { obv[j] = -1.0f; obi[j] = 0x7fffffff; }

        #pragma unroll
        for (int i = 0; i < K1_PPT; i++) {
            int p = base + tid + i * K1_TPB;
            #pragma unroll
            for (int j = 0; j < 4; j++) {
                float ix1 = fmaxf(B1[j], px1[i]), iy1 = fmaxf(B2[j], py1[i]);
                float ix2 = fminf(B3[j], px2[i]), iy2 = fminf(B4[j], py2[i]);
                float iw  = __saturatef(ix2 - ix1);   // FADD.SAT (fma pipe)
                float ih  = __saturatef(iy2 - iy1);
                float inter = iw * ih;
                float uni   = (BA[j] + pa[i]) - inter;
                float iou   = __fdividef(inter, uni);
                unsigned k = (__float_as_uint(iou) & 0xFFFFFFE0u)
                           | (unsigned)(31 - (g * 4 + j));
                pkey[i] = (k > pkey[i]) ? k : pkey[i];
                if (iou > obv[j]) { obv[j] = iou; obi[j] = p; }
            }
        }
        #pragma unroll
        for (int j = 0; j < 4; j++) {
            float v = obv[j]; int ix = obi[j];
            #pragma unroll
            for (int o = 16; o > 0; o >>= 1) {
                float v2 = __shfl_down_sync(0xffffffffu, v, o);
                int   i2 = __shfl_down_sync(0xffffffffu, ix, o);
                if (v2 > v || (v2 == v && i2 < ix)) { v = v2; ix = i2; }
            }
            if (lane == 0) { swv[j][wid] = v; swi[j][wid] = ix; }
        }
        __syncthreads();
        if (tid < 32) {
            int j = lane >> 3, w = lane & 7;
            float v = swv[j][w]; int ix = swi[j][w];
            #pragma unroll
            for (int o = 4; o > 0; o >>= 1) {
                float v2 = __shfl_down_sync(0xffffffffu, v, o);
                int   i2 = __shfl_down_sync(0xffffffffu, ix, o);
                if (v2 > v || (v2 == v && i2 < ix)) { v = v2; ix = i2; }
            }
            if (w == 0) {
                unsigned long long pk =
                    ((unsigned long long)__float_as_uint(v) << 32) | (unsigned)(~ix);
                g_objc[((size_t)b * NO + g * 4 + j) * NCHI + chunk] = pk;
            }
        }
        __syncthreads();
    }

    #pragma unroll
    for (int i = 0; i < K1_PPT; i++) {
        int pl = tid + i * K1_TPB;
        int p  = base + pl;
        if (pl < CPI && p < NP)
            g_pbest[(size_t)b * NP + p] = pkey[i];
    }
}

// ---------------------------------------------------------
// K2: match fix-up + CE + loc with warp-local smem transpose staging.
// grid = (NCHC, NB), 256 threads, 4 blocks/SM.
// ---------------------------------------------------------
__global__ __launch_bounds__(K2_TPB, 4)
void ce_k(const float* __restrict__ pred_loc,
          const float* __restrict__ pred_cls,
          const float* __restrict__ b_boxes,
          const int*   __restrict__ b_labels,
          const float* __restrict__ priors) {
    const int chunk = blockIdx.x;
    const int b     = blockIdx.y;
    const int tid   = threadIdx.x;
    const int lane  = tid & 31;
    const int wid   = tid >> 5;       // 0..7
    const int pbase = chunk * CPC0;
    const int cpc   = (chunk < 3) ? CPC0 : (NP - 3 * CPC0);
    const int pend  = pbase + cpc;

    __shared__ float sstage[8][32 * NC];     // 8 warps x 672 floats = 21504 B
    __shared__ float sbx1[NO], sby1[NO], sbx2[NO], sby2[NO];
    __shared__ int   slab[NO];
    __shared__ unsigned long long spk[NO];
    __shared__ unsigned char sov[CPC0];
    __shared__ int    siw[8];
    __shared__ double sdw[8], sdw2[8];

    if (tid < NO) {
        const float* bb = b_boxes + ((size_t)b * NO + tid) * 4;
        sbx1[tid] = bb[0]; sby1[tid] = bb[1]; sbx2[tid] = bb[2]; sby2[tid] = bb[3];
        slab[tid] = b_labels[b * NO + tid];
        unsigned long long mx = 0ULL;
        #pragma unroll
        for (int ch = 0; ch < NCHI; ch++) {
            unsigned long long v = g_objc[((size_t)b * NO + tid) * NCHI + ch];
            if (v > mx) mx = v;
        }
        spk[tid] = mx;
    }
    for (int i = tid; i < cpc; i += K2_TPB) sov[i] = 255;
    __syncthreads();
    if (tid == 0) {
        for (int m = NO - 1; m >= 0; --m) {     // descending: min m wins
            int p = (int)(~(unsigned)(spk[m] & 0xffffffffu));
            int r = p - pbase;
            if (r >= 0 && r < cpc) sov[r] = (unsigned char)m;
        }
    }
    __syncthreads();

    float* stw = &sstage[wid][0];
    int    npl  = 0;
    double cpl  = 0.0;
    double locl = 0.0;

    for (int it = 0; it < K2_ITERS; ++it) {
        int p0 = pbase + it * K2_TPB + wid * 32;
        if (p0 < pend) {                       // warp-uniform condition
            int avail = pend - p0;
            if (avail >= 32) {
                // contiguous 2688B span: 168 coalesced float4
                const float4* src = reinterpret_cast<const float4*>(pred_cls)
                                  + ((size_t)b * NP + p0) * NC / 4;
                #pragma unroll
                for (int r = 0; r < 6; ++r) {
                    int f = r * 32 + lane;
                    if (f < (32 * NC) / 4)
                        reinterpret_cast<float4*>(stw)[f] = src[f];
                }
            } else {
                const float* src = pred_cls + ((size_t)b * NP + p0) * NC;
                for (int e = lane; e < 32 * NC; e += 32)
                    stw[e] = (e < avail * NC) ? src[e] : 0.0f;
            }
            __syncwarp();

            int p = p0 + lane;
            if (p < pend) {
                unsigned pk = g_pbest[(size_t)b * NP + p];   // coalesced
                float bv = __uint_as_float(pk & 0xFFFFFFE0u);
                int   m  = 31 - (int)(pk & 31u);
                int ov = sov[p - pbase];
                if (ov != 255) {
                    if (bv < 1.0f || (bv == 1.0f && ov < m)) { bv = 1.0f; m = ov; }
                }
                bool pos = (bv >= THRESH);
                int  cls = pos ? slab[m] : 0;

                const float* row = stw + lane * NC;   // stride 21: conflict-free
                float se = 0.0f;
                #pragma unroll
                for (int c = 0; c < NC; ++c) se += __expf(row[c]);
                float ce = __logf(se) - row[cls];

                if (pos) {
                    g_ce[(size_t)b * NP + p] = 0.0f;
                    npl++;
                    cpl += (double)ce;
                    float4 pc = reinterpret_cast<const float4*>(priors)[p];
                    float x1 = sbx1[m], y1 = sby1[m], x2 = sbx2[m], y2 = sby2[m];
                    float cx = (x1 + x2) * 0.5f, cy = (y1 + y2) * 0.5f;
                    float bw = x2 - x1, bh = y2 - y1;
                    float gx = (cx - pc.x) / (pc.z / 10.0f);
                    float gy = (cy - pc.y) / (pc.w / 10.0f);
                    float gw = __logf(bw / pc.z) * 5.0f;
                    float gh = __logf(bh / pc.w) * 5.0f;
                    float4 pl = reinterpret_cast<const float4*>(pred_loc)[(size_t)b * NP + p];
                    locl += (double)(fabsf(pl.x - gx) + fabsf(pl.y - gy) +
                                     fabsf(pl.z - gw) + fabsf(pl.w - gh));
                } else {
                    g_ce[(size_t)b * NP + p] = fmaxf(ce, 0.0f);
                }
            }
            __syncwarp();   // protect stage before next iteration overwrites
        }
    }

    // block reduce -> per-chunk plain stores (no atomics, deterministic)
    #pragma unroll
    for (int o = 16; o > 0; o >>= 1) {
        npl  += __shfl_down_sync(0xffffffffu, npl, o);
        cpl  += __shfl_down_sync(0xffffffffu, cpl, o);
        locl += __shfl_down_sync(0xffffffffu, locl, o);
    }
    if (lane == 0) { siw[wid] = npl; sdw[wid] = cpl; sdw2[wid] = locl; }
    __syncthreads();
    if (tid == 0) {
        int n = 0; double c = 0.0, l = 0.0;
        #pragma unroll
        for (int w = 0; w < 8; w++) { n += siw[w]; c += sdw[w]; l += sdw2[w]; }
        g_npc[b * NCHC + chunk]  = n;
        g_cpc[b * NCHC + chunk]  = c;
        g_locc[b * NCHC + chunk] = l;
    }
}

// ---------------------------------------------------------
// K3: exact top-K via register radix select (REDUX counts) + fused finalize.
// grid = NB, 512 threads.
// ---------------------------------------------------------
__global__ __launch_bounds__(K3_TPB)
void hard_k(float* __restrict__ out) {
    const int b    = blockIdx.x;
    const int tid  = threadIdx.x;
    const int lane = tid & 31;
    const int wid  = tid >> 5;      // 0..15

    __shared__ int    sscnt[32];
    __shared__ int    siw[16];
    __shared__ double sdw[16];
    __shared__ double sl2[16];
    __shared__ bool   s_last;

    unsigned v[K3_VPT];
    #pragma unroll
    for (int i = 0; i < K3_VPT; i++) {
        int p = tid + i * K3_TPB;
        v[i] = (p < NP) ? __float_as_uint(g_ce[(size_t)b * NP + p]) : 0u;
    }
    if (tid < 32) sscnt[tid] = 0;
    int K = g_npc[b * NCHC + 0] + g_npc[b * NCHC + 1]
          + g_npc[b * NCHC + 2] + g_npc[b * NCHC + 3];
    K *= 3;
    if (K > NP) K = NP;
    __syncthreads();

    unsigned t = 0u;
    for (int bit = 30; bit >= 0; --bit) {
        unsigned cand = t | (1u << bit);
        int c = 0;
        #pragma unroll
        for (int i = 0; i < K3_VPT; i++)
            if (v[i] >= cand) c++;
        c = __reduce_add_sync(0xffffffffu, c);   // REDUX.SUM
        if (lane == 0 && c) atomicAdd(&sscnt[bit], c);
        __syncthreads();
        if (sscnt[bit] >= K) t = cand;
    }

    int    cgt = 0;
    double sg  = 0.0;
    #pragma unroll
    for (int i = 0; i < K3_VPT; i++) {
        if (v[i] > t) { cgt++; sg += (double)__uint_as_float(v[i]); }
    }
    cgt = __reduce_add_sync(0xffffffffu, cgt);
    #pragma unroll
    for (int o = 16; o > 0; o >>= 1)
        sg += __shfl_down_sync(0xffffffffu, sg, o);
    if (lane == 0) { siw[wid] = cgt; sdw[wid] = sg; }
    __syncthreads();
    if (tid == 0) {
        int c = 0; double sm = 0.0;
        #pragma unroll
        for (int w = 0; w < 16; w++) { c += siw[w]; sm += sdw[w]; }
        g_hard[b] = sm + (double)(K - c) * (double)__uint_as_float(t);
        __threadfence();
        unsigned n = atomicAdd(&g_done, 1u);
        s_last = (n == NB - 1);
    }
    __syncthreads();

    if (s_last) {
        if (tid == 0) g_done = 0;   // reset for next graph replay
        double h = 0.0, l = 0.0; int n = 0;
        if (tid < NB) {
            h = g_hard[tid];
            #pragma unroll
            for (int ch = 0; ch < NCHC; ch++) {
                h += g_cpc[tid * NCHC + ch];
                l += g_locc[tid * NCHC + ch];
                n += g_npc[tid * NCHC + ch];
            }
        }
        #pragma unroll
        for (int o = 16; o > 0; o >>= 1) {
            h += __shfl_down_sync(0xffffffffu, h, o);
            l += __shfl_down_sync(0xffffffffu, l, o);
            n += __shfl_down_sync(0xffffffffu, n, o);
        }
        if (lane == 0) { sdw[wid] = h; sl2[wid] = l; siw[wid] = n; }
        __syncthreads();
        if (tid == 0) {
            double H = 0.0, L = 0.0, N = 0.0;
            #pragma unroll
            for (int w = 0; w < 16; w++) { H += sdw[w]; L += sl2[w]; N += (double)siw[w]; }
            double loc  = ALPHA * (L / (N * 4.0));
            double conf = H / N;
            out[0] = (float)(conf + loc);
            out[1] = (float)loc;
            out[2] = (float)conf;
        }
    }
}

extern "C" void kernel_launch(void* const* d_in, const int* in_sizes, int n_in,
                              void* d_out, int out_size) {
    const float* pred_loc = (const float*)d_in[0];
    const float* pred_cls = (const float*)d_in[1];
    const float* b_boxes  = (const float*)d_in[2];
    const int*   b_labels = (const int*)  d_in[3];
    const float* priors   = (const float*)d_in[4];
    float* out = (float*)d_out;

    iou_k<<<dim3(NCHI, NB), K1_TPB>>>(b_boxes, priors);
    ce_k<<<dim3(NCHC, NB), K2_TPB>>>(pred_loc, pred_cls, b_boxes, b_labels, priors);
    hard_k<<<NB, K3_TPB>>>(out);
}